// round 1
// baseline (speedup 1.0000x reference)
#include <cuda_runtime.h>

// Fused 3-stage mode-contraction (Tucker transform) per batch element.
// Each stage: out[m*32 + i] = sum_c in[c*1024 + m] * w[c*32 + i]
// applied 3x (w0, w1, w2) on a 32x32x32 fp32 tile held entirely in smem.
//
// Layout proof:
//   x[b][f1][f2][f3]                      -> in[c=f1][m=f2*32+f3]
//   stage1 out = A[f2][f3][i]   (flat: m*32+i)  == in[c=f2][m'=f3*32+i]
//   stage2 out = B[f3][i][j]                     == in[c=f3][m''=i*32+j]
//   stage3 out = C[i][j][k]  == reference out[b] row-major.

#define NTHREADS 512
#define TILE 32768            // 32*32*32 floats per batch element

__global__ __launch_bounds__(NTHREADS, 1)
void tucker3_kernel(const float* __restrict__ x,
                    const float* __restrict__ w0,
                    const float* __restrict__ w1,
                    const float* __restrict__ w2,
                    float* __restrict__ out)
{
    extern __shared__ float smem[];
    float* S = smem;            // 32768 floats: data tile (in-place per stage)
    float* W = smem + TILE;     // 3 * 1024 floats: weights

    const int tid = threadIdx.x;
    const long base = (long)blockIdx.x * TILE;

    // Load all three 32x32 weight matrices into smem.
    for (int i = tid; i < 1024; i += NTHREADS) {
        W[i]        = w0[i];
        W[1024 + i] = w1[i];
        W[2048 + i] = w2[i];
    }

    // Coalesced float4 load of the 128KB tile.
    {
        const float4* xg = (const float4*)(x + base);
        float4* S4 = (float4*)S;
        #pragma unroll
        for (int i = 0; i < TILE / 4 / NTHREADS; i++)   // 16 iters
            S4[tid + i * NTHREADS] = xg[tid + i * NTHREADS];
    }
    __syncthreads();

    // Thread tile: 8 m-values x 8 i-values (64 accumulators).
    // Warp covers 64 consecutive m x 32 i.
    const int warp  = tid >> 5;
    const int lane  = tid & 31;
    const int tm    = lane >> 2;            // 0..7
    const int ti    = lane & 3;             // 0..3
    const int mBase = warp * 64 + tm * 8;   // 8 consecutive m per thread
    const int iBase = ti * 8;               // 8 consecutive i per thread

    for (int s = 0; s < 3; s++) {
        const float* __restrict__ Wc = W + s * 1024;

        float acc[8][8];
        #pragma unroll
        for (int a = 0; a < 8; a++)
            #pragma unroll
            for (int q = 0; q < 8; q++)
                acc[a][q] = 0.0f;

        #pragma unroll 4
        for (int c = 0; c < 32; c++) {
            float4 xa = *(const float4*)&S[c * 1024 + mBase];
            float4 xb = *(const float4*)&S[c * 1024 + mBase + 4];
            float4 wa = *(const float4*)&Wc[c * 32 + iBase];
            float4 wb = *(const float4*)&Wc[c * 32 + iBase + 4];

            float xs[8] = {xa.x, xa.y, xa.z, xa.w, xb.x, xb.y, xb.z, xb.w};
            float ws[8] = {wa.x, wa.y, wa.z, wa.w, wb.x, wb.y, wb.z, wb.w};

            #pragma unroll
            for (int a = 0; a < 8; a++)
                #pragma unroll
                for (int q = 0; q < 8; q++)
                    acc[a][q] = fmaf(xs[a], ws[q], acc[a][q]);
        }

        __syncthreads();   // all reads of S for this stage are done

        // Write out[m*32 + i] back into S (transposed layout for next stage).
        #pragma unroll
        for (int a = 0; a < 8; a++) {
            const int m = mBase + a;
            float4 v0 = make_float4(acc[a][0], acc[a][1], acc[a][2], acc[a][3]);
            float4 v1 = make_float4(acc[a][4], acc[a][5], acc[a][6], acc[a][7]);
            *(float4*)&S[m * 32 + iBase]     = v0;
            *(float4*)&S[m * 32 + iBase + 4] = v1;
        }
        __syncthreads();
    }

    // Coalesced float4 store of the final tile.
    {
        float4* og = (float4*)(out + base);
        const float4* S4 = (const float4*)S;
        #pragma unroll
        for (int i = 0; i < TILE / 4 / NTHREADS; i++)
            og[tid + i * NTHREADS] = S4[tid + i * NTHREADS];
    }
}

extern "C" void kernel_launch(void* const* d_in, const int* in_sizes, int n_in,
                              void* d_out, int out_size)
{
    const float* x  = (const float*)d_in[0];
    const float* w0 = (const float*)d_in[1];
    const float* w1 = (const float*)d_in[2];
    const float* w2 = (const float*)d_in[3];
    float* out = (float*)d_out;

    const int nBatch = in_sizes[0] >> 15;   // elements / 32768

    const size_t smemBytes = (TILE + 3 * 1024) * sizeof(float);  // 143360
    cudaFuncSetAttribute(tucker3_kernel,
                         cudaFuncAttributeMaxDynamicSharedMemorySize,
                         (int)smemBytes);

    tucker3_kernel<<<nBatch, NTHREADS, smemBytes>>>(x, w0, w1, w2, out);
}